// round 14
// baseline (speedup 1.0000x reference)
#include <cuda_runtime.h>
#include <cuda_bf16.h>
#include <cstdint>

#define B_      64
#define WVEC    50890
#define NTEST   10000
#define INPUT_  784
#define KPAD    832    // 13 * 64
#define NCHUNK  13
#define HIDDEN_ 64
#define OUT_    10
#define O1 50176
#define O2 50240
#define O3 50880
#define NTILE_  79    // ceil(10000/128)
#define PREPB   1024  // prep kernel blocks

__device__ double g_acc2;
__device__ float  g_l1part[PREPB];
__device__ __nv_bfloat16 g_imgs_bf[NTEST * KPAD];          // 16.6 MB (K zero-padded)
__device__ __nv_bfloat16 g_w1_bf[B_ * HIDDEN_ * KPAD];     // 6.8 MB

// ---------------- fused prep: conversions + loss1 partials ----------------
__global__ __launch_bounds__(256) void prep_k(const float* __restrict__ images,
                                              const float* __restrict__ w,
                                              const float* __restrict__ a,
                                              const float* __restrict__ t) {
    if (blockIdx.x == 0 && threadIdx.x == 0) g_acc2 = 0.0;
    const int gtid = blockIdx.x * blockDim.x + threadIdx.x;
    const int gstr = gridDim.x * blockDim.x;

    // images fp32 -> bf16, K padded to 832
    {
        const int total = NTEST * KPAD / 2;
        __nv_bfloat162* dst = (__nv_bfloat162*)g_imgs_bf;
        for (int i = gtid; i < total; i += gstr) {
            int p = i % (KPAD / 2), row = i / (KPAD / 2);
            int k = 2 * p;
            __nv_bfloat162 v;
            if (k < INPUT_) {
                float2 f = *(const float2*)(images + (size_t)row * INPUT_ + k);
                v = __floats2bfloat162_rn(f.x, f.y);
            } else {
                v = __floats2bfloat162_rn(0.f, 0.f);
            }
            dst[i] = v;
        }
    }
    // W1 fp32 -> bf16, K padded
    {
        const int total = B_ * HIDDEN_ * KPAD / 2;
        __nv_bfloat162* dst = (__nv_bfloat162*)g_w1_bf;
        for (int i = gtid; i < total; i += gstr) {
            int p = i % (KPAD / 2), r = i / (KPAD / 2);
            int b = r >> 6, j = r & 63;
            int k = 2 * p;
            __nv_bfloat162 v;
            if (k < INPUT_) {
                float2 f = *(const float2*)(w + (size_t)b * WVEC + j * INPUT_ + k);
                v = __floats2bfloat162_rn(f.x, f.y);
            } else {
                v = __floats2bfloat162_rn(0.f, 0.f);
            }
            dst[i] = v;
        }
    }
    // loss1 partial sum for this block
    {
        const int total4 = (B_ * WVEC) / 4;
        float s = 0.f;
        for (int i = gtid; i < total4; i += gstr) {
            float4 x = ((const float4*)a)[i];
            float4 y = ((const float4*)t)[i];
            float d0 = x.x - y.x, d1 = x.y - y.y, d2 = x.z - y.z, d3 = x.w - y.w;
            s += d0 * d0 + d1 * d1 + d2 * d2 + d3 * d3;
        }
        #pragma unroll
        for (int off = 16; off; off >>= 1) s += __shfl_down_sync(0xffffffffu, s, off);
        __shared__ float ws[8];
        int lane = threadIdx.x & 31, wrp = threadIdx.x >> 5;
        if (lane == 0) ws[wrp] = s;
        __syncthreads();
        if (threadIdx.x == 0) {
            float tot = 0.f;
            #pragma unroll
            for (int i = 0; i < 8; i++) tot += ws[i];
            g_l1part[blockIdx.x] = tot;
        }
    }
}

__device__ __forceinline__ uint32_t smem_u32(const void* p) {
    uint32_t a;
    asm("{ .reg .u64 t; cvta.to.shared.u64 t, %1; cvt.u32.u64 %0, t; }" : "=r"(a) : "l"(p));
    return a;
}
#define CP16(dst, src) \
    asm volatile("cp.async.cg.shared.global [%0], [%1], 16;" :: "r"(dst), "l"(src))
#define CP_COMMIT() asm volatile("cp.async.commit_group;" ::: "memory")
#define CP_WAIT(n)  asm volatile("cp.async.wait_group %0;" :: "n"(n) : "memory")
#define LDSM_X4(r0, r1, r2, r3, addr) \
    asm volatile("ldmatrix.sync.aligned.m8n8.x4.shared.b16 {%0,%1,%2,%3}, [%4];" \
                 : "=r"(r0), "=r"(r1), "=r"(r2), "=r"(r3) : "r"(addr))

// ------------- bf16 mma.sync MLP forward + CE (KC=64, dynamic smem) ------------
// CTA: 256 thr (8 warps = 4 m-strips x 2 b). Tile M=128 imgs, N=2x64 hidden, K=832.
#define TSTRIDE 72                       // bf16 elems per smem row (144 B)
#define TBYTES   (128 * TSTRIDE * 2)     // 18432 B per tensor per stage
#define STAGE_T  (2 * TBYTES)            // 36864 B per stage (A then B)
#define TAB_OFF  (2 * STAGE_T)           // 73728
#define SMEM_TOT (TAB_OFF + 5120 + 512 + 80 + 32)   // 79472

__global__ __launch_bounds__(256, 2) void mlp_ce_mma_k(const float* __restrict__ w,
                                                       const int* __restrict__ tar2) {
    extern __shared__ char dyn[];
    const int bp = blockIdx.y;
    const int n0 = blockIdx.x * 128;

    float* w2s = (float*)(dyn + TAB_OFF);         // 1280 floats
    float* b1s = w2s + 2 * OUT_ * HIDDEN_;        // 128
    float* b2s = b1s + 2 * HIDDEN_;               // 20
    float* warpsum = b2s + 2 * OUT_;              // 8

    const int tid = threadIdx.x, wid = tid >> 5, lane = tid & 31;
    const int wm = wid & 3, wn = wid >> 2;
    const int g = lane >> 2, t = lane & 3;

    // stage-2 weights (scalar loads: alignment-safe)
    #pragma unroll 1
    for (int i = tid; i < 2 * OUT_ * HIDDEN_; i += 256) {
        int bb = i / (OUT_ * HIDDEN_), r = i % (OUT_ * HIDDEN_);
        w2s[i] = w[(size_t)(2 * bp + bb) * WVEC + O2 + r];
    }
    if (tid < 128) b1s[tid] = w[(size_t)(2 * bp + (tid >> 6)) * WVEC + O1 + (tid & 63)];
    if (tid < 20)  b2s[tid] = w[(size_t)(2 * bp + (tid >= 10)) * WVEC + O3 + (tid % 10)];

    float acc[2][8][4];
    #pragma unroll
    for (int mt = 0; mt < 2; mt++)
        #pragma unroll
        for (int nt = 0; nt < 8; nt++)
            #pragma unroll
            for (int r = 0; r < 4; r++) acc[mt][nt][r] = 0.f;

    const __nv_bfloat16* Ab = g_imgs_bf;
    const __nv_bfloat16* Bb = g_w1_bf + (size_t)(2 * bp) * HIDDEN_ * KPAD;

    // cp.async: 2 threads/row, each half copies 64 B = 4x16B chunks (row = 128 B)
    const int rowT = tid >> 1, eT = (tid & 1) * 32;
    int gnT = n0 + rowT; if (gnT > NTEST - 1) gnT = NTEST - 1;
    const __nv_bfloat16* srcA = Ab + (size_t)gnT * KPAD + eT;
    const __nv_bfloat16* srcB = Bb + (size_t)rowT * KPAD + eT;
    const uint32_t dynU = smem_u32(dyn);
    const uint32_t dstA = dynU + rowT * (TSTRIDE * 2) + eT * 2;
    const uint32_t dstB = dynU + TBYTES + rowT * (TSTRIDE * 2) + eT * 2;

    // ldmatrix base addresses (stage 0, ks = 0)
    uint32_t aAddr[2], bAddr[4];
    #pragma unroll
    for (int mt = 0; mt < 2; mt++)
        aAddr[mt] = dynU + (((wm * 32 + mt * 16 + (lane & 15)) * TSTRIDE) +
                            ((lane >> 4) * 8)) * 2;
    #pragma unroll
    for (int ntp = 0; ntp < 4; ntp++)
        bAddr[ntp] = dynU + TBYTES +
                     (((wn * 64 + ntp * 16 + ((lane >> 4) * 8) + (lane & 7)) * TSTRIDE) +
                      (((lane >> 3) & 1) * 8)) * 2;

    // prologue: stage 0
    #pragma unroll
    for (int q = 0; q < 4; q++) {
        CP16(dstA + q * 16, srcA + q * 8);
        CP16(dstB + q * 16, srcB + q * 8);
    }
    CP_COMMIT();

    for (int c = 0; c < NCHUNK; c++) {
        CP_WAIT(0);
        // one barrier: publishes stage c AND proves all warps finished compute
        // of c-1 -> safe to overwrite stage (c+1)&1 below
        __syncthreads();
        if (c < NCHUNK - 1) {
            const uint32_t pOff = (uint32_t)((c + 1) & 1) * STAGE_T;
            const int k0 = (c + 1) * 64;
            #pragma unroll
            for (int q = 0; q < 4; q++) {
                CP16(dstA + pOff + q * 16, srcA + k0 + q * 8);
                CP16(dstB + pOff + q * 16, srcB + k0 + q * 8);
            }
            CP_COMMIT();
        }
        const uint32_t stOff = (uint32_t)(c & 1) * STAGE_T;
        #pragma unroll
        for (int ks = 0; ks < 4; ks++) {
            const uint32_t ko = stOff + ks * 32;   // 16 bf16 = 32 B
            uint32_t a[2][4], bf[8][2];
            LDSM_X4(a[0][0], a[0][1], a[0][2], a[0][3], aAddr[0] + ko);
            LDSM_X4(a[1][0], a[1][1], a[1][2], a[1][3], aAddr[1] + ko);
            LDSM_X4(bf[0][0], bf[0][1], bf[1][0], bf[1][1], bAddr[0] + ko);
            LDSM_X4(bf[2][0], bf[2][1], bf[3][0], bf[3][1], bAddr[1] + ko);
            LDSM_X4(bf[4][0], bf[4][1], bf[5][0], bf[5][1], bAddr[2] + ko);
            LDSM_X4(bf[6][0], bf[6][1], bf[7][0], bf[7][1], bAddr[3] + ko);
            #pragma unroll
            for (int mt = 0; mt < 2; mt++)
                #pragma unroll
                for (int nt = 0; nt < 8; nt++)
                    asm volatile(
                        "mma.sync.aligned.m16n8k16.row.col.f32.bf16.bf16.f32 "
                        "{%0,%1,%2,%3},{%4,%5,%6,%7},{%8,%9},{%0,%1,%2,%3};"
                        : "+f"(acc[mt][nt][0]), "+f"(acc[mt][nt][1]),
                          "+f"(acc[mt][nt][2]), "+f"(acc[mt][nt][3])
                        : "r"(a[mt][0]), "r"(a[mt][1]), "r"(a[mt][2]), "r"(a[mt][3]),
                          "r"(bf[nt][0]), "r"(bf[nt][1]));
        }
    }

    // ---- stage 2 straight from fragments ----
    float lg[4][OUT_];
    #pragma unroll
    for (int r = 0; r < 4; r++)
        #pragma unroll
        for (int o = 0; o < OUT_; o++) lg[r][o] = 0.f;

    #pragma unroll
    for (int nt = 0; nt < 8; nt++) {
        #pragma unroll
        for (int e = 0; e < 2; e++) {
            const int j = nt * 8 + 2 * t + e;
            const float bias = b1s[wn * 64 + j];
            float wv[OUT_];
            #pragma unroll
            for (int o = 0; o < OUT_; o++) wv[o] = w2s[wn * 640 + o * 64 + j];
            #pragma unroll
            for (int mt = 0; mt < 2; mt++)
                #pragma unroll
                for (int h = 0; h < 2; h++) {
                    float hv = fmaxf(acc[mt][nt][h * 2 + e] + bias, 0.f);
                    #pragma unroll
                    for (int o = 0; o < OUT_; o++)
                        lg[mt * 2 + h][o] = fmaf(hv, wv[o], lg[mt * 2 + h][o]);
                }
        }
    }
    #pragma unroll
    for (int r = 0; r < 4; r++)
        #pragma unroll
        for (int o = 0; o < OUT_; o++) {
            lg[r][o] += __shfl_xor_sync(0xffffffffu, lg[r][o], 1);
            lg[r][o] += __shfl_xor_sync(0xffffffffu, lg[r][o], 2);
        }

    float ce = 0.f;
    if (t == 0) {
        const int bidx = 2 * bp + wn;
        #pragma unroll
        for (int mt = 0; mt < 2; mt++)
            #pragma unroll
            for (int h = 0; h < 2; h++) {
                const int gn = n0 + wm * 32 + mt * 16 + g + 8 * h;
                if (gn < NTEST) {
                    float logits[OUT_];
                    #pragma unroll
                    for (int o = 0; o < OUT_; o++)
                        logits[o] = lg[mt * 2 + h][o] + b2s[wn * 10 + o];
                    float m = logits[0];
                    #pragma unroll
                    for (int o = 1; o < OUT_; o++) m = fmaxf(m, logits[o]);
                    float s = 0.f;
                    #pragma unroll
                    for (int o = 0; o < OUT_; o++) s += expf(logits[o] - m);
                    float lse = m + logf(s);
                    int tg = tar2[(size_t)bidx * NTEST + gn];
                    float picked = 0.f;
                    #pragma unroll
                    for (int o = 0; o < OUT_; o++) picked = (o == tg) ? logits[o] : picked;
                    ce += lse - picked;
                }
            }
    }
    #pragma unroll
    for (int off = 16; off; off >>= 1) ce += __shfl_down_sync(0xffffffffu, ce, off);
    if (lane == 0) warpsum[wid] = ce;
    __syncthreads();
    if (tid == 0) {
        float tot = 0.f;
        #pragma unroll
        for (int i = 0; i < 8; i++) tot += warpsum[i];
        atomicAdd(&g_acc2, (double)tot);
    }
}

// ---------------- finalize: reduce loss1 partials + combine ----------------
__global__ __launch_bounds__(256) void fin_k(float* __restrict__ out) {
    __shared__ float ws[8];
    float s = 0.f;
    for (int i = threadIdx.x; i < PREPB; i += 256) s += g_l1part[i];
    #pragma unroll
    for (int off = 16; off; off >>= 1) s += __shfl_down_sync(0xffffffffu, s, off);
    int lane = threadIdx.x & 31, wrp = threadIdx.x >> 5;
    if (lane == 0) ws[wrp] = s;
    __syncthreads();
    if (threadIdx.x == 0) {
        float tot = 0.f;
        #pragma unroll
        for (int i = 0; i < 8; i++) tot += ws[i];
        float l1 = (float)(20.0 * ((double)tot / (double)((size_t)B_ * WVEC)));
        float l2 = (float)(g_acc2 / (double)((size_t)B_ * NTEST));
        out[0] = l1 + l2;
        out[1] = l1;
        out[2] = l2;
    }
}

extern "C" void kernel_launch(void* const* d_in, const int* in_sizes, int n_in,
                              void* d_out, int out_size) {
    const float* inp1   = (const float*)d_in[0];
    const float* tar1   = (const float*)d_in[1];
    const float* inp2   = (const float*)d_in[2];
    const int*   tar2   = (const int*)d_in[3];
    const float* images = (const float*)d_in[4];
    float* out = (float*)d_out;

    cudaFuncSetAttribute(mlp_ce_mma_k,
                         cudaFuncAttributeMaxDynamicSharedMemorySize, SMEM_TOT);

    prep_k<<<PREPB, 256>>>(images, inp2, inp1, tar1);
    dim3 grid(NTILE_, B_ / 2);
    mlp_ce_mma_k<<<grid, 256, SMEM_TOT>>>(inp2, tar2);
    fin_k<<<1, 256>>>(out);
}

// round 15
// speedup vs baseline: 1.1492x; 1.1492x over previous
#include <cuda_runtime.h>
#include <cuda_bf16.h>
#include <cstdint>

#define B_      64
#define WVEC    50890
#define NTEST   10000
#define INPUT_  784
#define KPAD    800
#define NCHUNK  25
#define HIDDEN_ 64
#define OUT_    10
#define O1 50176
#define O2 50240
#define O3 50880
#define NTILE_  79    // ceil(10000/128)
#define PREPB   1024  // prep kernel blocks

__device__ double g_acc2;
__device__ float  g_l1part[PREPB];
__device__ __nv_bfloat16 g_imgs_bf[NTEST * KPAD];          // 16 MB (K zero-padded)
__device__ __nv_bfloat16 g_w1_bf[B_ * HIDDEN_ * KPAD];     // 6.6 MB

// ---------------- fused prep: conversions + loss1 partials ----------------
__global__ __launch_bounds__(256) void prep_k(const float* __restrict__ images,
                                              const float* __restrict__ w,
                                              const float* __restrict__ a,
                                              const float* __restrict__ t) {
    if (blockIdx.x == 0 && threadIdx.x == 0) g_acc2 = 0.0;
    const int gtid = blockIdx.x * blockDim.x + threadIdx.x;
    const int gstr = gridDim.x * blockDim.x;

    {
        const int total = NTEST * KPAD / 2;
        __nv_bfloat162* dst = (__nv_bfloat162*)g_imgs_bf;
        for (int i = gtid; i < total; i += gstr) {
            int p = i % (KPAD / 2), row = i / (KPAD / 2);
            int k = 2 * p;
            __nv_bfloat162 v;
            if (k < INPUT_) {
                float2 f = *(const float2*)(images + (size_t)row * INPUT_ + k);
                v = __floats2bfloat162_rn(f.x, f.y);
            } else {
                v = __floats2bfloat162_rn(0.f, 0.f);
            }
            dst[i] = v;
        }
    }
    {
        const int total = B_ * HIDDEN_ * KPAD / 2;
        __nv_bfloat162* dst = (__nv_bfloat162*)g_w1_bf;
        for (int i = gtid; i < total; i += gstr) {
            int p = i % (KPAD / 2), r = i / (KPAD / 2);
            int b = r >> 6, j = r & 63;
            int k = 2 * p;
            __nv_bfloat162 v;
            if (k < INPUT_) {
                float2 f = *(const float2*)(w + (size_t)b * WVEC + j * INPUT_ + k);
                v = __floats2bfloat162_rn(f.x, f.y);
            } else {
                v = __floats2bfloat162_rn(0.f, 0.f);
            }
            dst[i] = v;
        }
    }
    {
        const int total4 = (B_ * WVEC) / 4;
        float s = 0.f;
        for (int i = gtid; i < total4; i += gstr) {
            float4 x = ((const float4*)a)[i];
            float4 y = ((const float4*)t)[i];
            float d0 = x.x - y.x, d1 = x.y - y.y, d2 = x.z - y.z, d3 = x.w - y.w;
            s += d0 * d0 + d1 * d1 + d2 * d2 + d3 * d3;
        }
        #pragma unroll
        for (int off = 16; off; off >>= 1) s += __shfl_down_sync(0xffffffffu, s, off);
        __shared__ float ws[8];
        int lane = threadIdx.x & 31, wrp = threadIdx.x >> 5;
        if (lane == 0) ws[wrp] = s;
        __syncthreads();
        if (threadIdx.x == 0) {
            float tot = 0.f;
            #pragma unroll
            for (int i = 0; i < 8; i++) tot += ws[i];
            g_l1part[blockIdx.x] = tot;
        }
    }
}

__device__ __forceinline__ uint32_t smem_u32(const void* p) {
    uint32_t a;
    asm("{ .reg .u64 t; cvta.to.shared.u64 t, %1; cvt.u32.u64 %0, t; }" : "=r"(a) : "l"(p));
    return a;
}
#define CP16(dst, src) \
    asm volatile("cp.async.cg.shared.global [%0], [%1], 16;" :: "r"(dst), "l"(src))
#define CP_COMMIT() asm volatile("cp.async.commit_group;" ::: "memory")
#define CP_WAIT(n)  asm volatile("cp.async.wait_group %0;" :: "n"(n) : "memory")
#define LDSM_X4(r0, r1, r2, r3, addr) \
    asm volatile("ldmatrix.sync.aligned.m8n8.x4.shared.b16 {%0,%1,%2,%3}, [%4];" \
                 : "=r"(r0), "=r"(r1), "=r"(r2), "=r"(r3) : "r"(addr))

// ------- bf16 mma.sync MLP forward + CE (KC=32, 4-stage ring, CP_WAIT(2)) ------
// CTA: 256 thr (8 warps = 4 m-strips x 2 b). Tile M=128 imgs, N=2x64 hidden, K=800.
#define TSTRIDE 40                       // bf16 elems per smem row (80 B)
#define TBYTES   (128 * TSTRIDE * 2)     // 10240 B per tensor per stage
#define STAGE_T  (2 * TBYTES)            // 20480 B per stage (A then B)
#define NSTAGE   4
#define TAB_OFF  (NSTAGE * STAGE_T)      // 81920
#define SMEM_TOT (TAB_OFF + 5120 + 512 + 80 + 32)   // 87664

__global__ __launch_bounds__(256, 2) void mlp_ce_mma_k(const float* __restrict__ w,
                                                       const int* __restrict__ tar2) {
    extern __shared__ char dyn[];
    const int bp = blockIdx.y;
    const int n0 = blockIdx.x * 128;

    float* w2s = (float*)(dyn + TAB_OFF);
    float* b1s = w2s + 2 * OUT_ * HIDDEN_;
    float* b2s = b1s + 2 * HIDDEN_;
    float* warpsum = b2s + 2 * OUT_;

    const int tid = threadIdx.x, wid = tid >> 5, lane = tid & 31;
    const int wm = wid & 3, wn = wid >> 2;
    const int g = lane >> 2, t = lane & 3;

    // stage-2 weights (scalar loads: alignment-safe)
    #pragma unroll 1
    for (int i = tid; i < 2 * OUT_ * HIDDEN_; i += 256) {
        int bb = i / (OUT_ * HIDDEN_), r = i % (OUT_ * HIDDEN_);
        w2s[i] = w[(size_t)(2 * bp + bb) * WVEC + O2 + r];
    }
    if (tid < 128) b1s[tid] = w[(size_t)(2 * bp + (tid >> 6)) * WVEC + O1 + (tid & 63)];
    if (tid < 20)  b2s[tid] = w[(size_t)(2 * bp + (tid >= 10)) * WVEC + O3 + (tid % 10)];

    float acc[2][8][4];
    #pragma unroll
    for (int mt = 0; mt < 2; mt++)
        #pragma unroll
        for (int nt = 0; nt < 8; nt++)
            #pragma unroll
            for (int r = 0; r < 4; r++) acc[mt][nt][r] = 0.f;

    const __nv_bfloat16* Ab = g_imgs_bf;
    const __nv_bfloat16* Bb = g_w1_bf + (size_t)(2 * bp) * HIDDEN_ * KPAD;

    // cp.async mapping: 2 threads/row, 2x16B chunks each (row = 32 bf16 = 64 B)
    const int rowT = tid >> 1, eT = (tid & 1) * 16;
    int gnT = n0 + rowT; if (gnT > NTEST - 1) gnT = NTEST - 1;
    const __nv_bfloat16* srcA = Ab + (size_t)gnT * KPAD + eT;
    const __nv_bfloat16* srcB = Bb + (size_t)rowT * KPAD + eT;
    const uint32_t dynU = smem_u32(dyn);
    const uint32_t dstA = dynU + rowT * (TSTRIDE * 2) + eT * 2;
    const uint32_t dstB = dynU + TBYTES + rowT * (TSTRIDE * 2) + eT * 2;

    // ldmatrix base addresses (stage 0, ks = 0)
    uint32_t aAddr[2], bAddr[4];
    #pragma unroll
    for (int mt = 0; mt < 2; mt++)
        aAddr[mt] = dynU + (((wm * 32 + mt * 16 + (lane & 15)) * TSTRIDE) +
                            ((lane >> 4) * 8)) * 2;
    #pragma unroll
    for (int ntp = 0; ntp < 4; ntp++)
        bAddr[ntp] = dynU + TBYTES +
                     (((wn * 64 + ntp * 16 + ((lane >> 4) * 8) + (lane & 7)) * TSTRIDE) +
                      (((lane >> 3) & 1) * 8)) * 2;

    // prologue: stages 0..2 (3 separate groups)
    #pragma unroll
    for (int s = 0; s < NSTAGE - 1; s++) {
        const uint32_t so = (uint32_t)s * STAGE_T;
        const int k0 = s * 32;
        CP16(dstA + so,      srcA + k0);
        CP16(dstA + so + 16, srcA + k0 + 8);
        CP16(dstB + so,      srcB + k0);
        CP16(dstB + so + 16, srcB + k0 + 8);
        CP_COMMIT();
    }

    for (int c = 0; c < NCHUNK; c++) {
        // exactly 3 groups outstanding at this point; wait for the oldest
        // (stage c's group, committed 3 iterations ago -> usually already done)
        CP_WAIT(2);
        // one barrier: publishes stage c to all warps AND proves all warps
        // finished compute of c-1 -> safe to overwrite stage (c+3)%4 below
        __syncthreads();
        if (c + NSTAGE - 1 < NCHUNK) {
            const uint32_t pOff = (uint32_t)((c + NSTAGE - 1) & 3) * STAGE_T;
            const int k0 = (c + NSTAGE - 1) * 32;
            CP16(dstA + pOff,      srcA + k0);
            CP16(dstA + pOff + 16, srcA + k0 + 8);
            CP16(dstB + pOff,      srcB + k0);
            CP16(dstB + pOff + 16, srcB + k0 + 8);
        }
        CP_COMMIT();   // unconditional: keeps outstanding-group count uniform
        const uint32_t stOff = (uint32_t)(c & 3) * STAGE_T;
        #pragma unroll
        for (int ks = 0; ks < 2; ks++) {
            const uint32_t ko = stOff + ks * 32;   // 16 bf16 = 32 B
            uint32_t a[2][4], bf[8][2];
            LDSM_X4(a[0][0], a[0][1], a[0][2], a[0][3], aAddr[0] + ko);
            LDSM_X4(a[1][0], a[1][1], a[1][2], a[1][3], aAddr[1] + ko);
            LDSM_X4(bf[0][0], bf[0][1], bf[1][0], bf[1][1], bAddr[0] + ko);
            LDSM_X4(bf[2][0], bf[2][1], bf[3][0], bf[3][1], bAddr[1] + ko);
            LDSM_X4(bf[4][0], bf[4][1], bf[5][0], bf[5][1], bAddr[2] + ko);
            LDSM_X4(bf[6][0], bf[6][1], bf[7][0], bf[7][1], bAddr[3] + ko);
            #pragma unroll
            for (int mt = 0; mt < 2; mt++)
                #pragma unroll
                for (int nt = 0; nt < 8; nt++)
                    asm volatile(
                        "mma.sync.aligned.m16n8k16.row.col.f32.bf16.bf16.f32 "
                        "{%0,%1,%2,%3},{%4,%5,%6,%7},{%8,%9},{%0,%1,%2,%3};"
                        : "+f"(acc[mt][nt][0]), "+f"(acc[mt][nt][1]),
                          "+f"(acc[mt][nt][2]), "+f"(acc[mt][nt][3])
                        : "r"(a[mt][0]), "r"(a[mt][1]), "r"(a[mt][2]), "r"(a[mt][3]),
                          "r"(bf[nt][0]), "r"(bf[nt][1]));
        }
    }

    // ---- stage 2 straight from fragments ----
    float lg[4][OUT_];
    #pragma unroll
    for (int r = 0; r < 4; r++)
        #pragma unroll
        for (int o = 0; o < OUT_; o++) lg[r][o] = 0.f;

    #pragma unroll
    for (int nt = 0; nt < 8; nt++) {
        #pragma unroll
        for (int e = 0; e < 2; e++) {
            const int j = nt * 8 + 2 * t + e;
            const float bias = b1s[wn * 64 + j];
            float wv[OUT_];
            #pragma unroll
            for (int o = 0; o < OUT_; o++) wv[o] = w2s[wn * 640 + o * 64 + j];
            #pragma unroll
            for (int mt = 0; mt < 2; mt++)
                #pragma unroll
                for (int h = 0; h < 2; h++) {
                    float hv = fmaxf(acc[mt][nt][h * 2 + e] + bias, 0.f);
                    #pragma unroll
                    for (int o = 0; o < OUT_; o++)
                        lg[mt * 2 + h][o] = fmaf(hv, wv[o], lg[mt * 2 + h][o]);
                }
        }
    }
    #pragma unroll
    for (int r = 0; r < 4; r++)
        #pragma unroll
        for (int o = 0; o < OUT_; o++) {
            lg[r][o] += __shfl_xor_sync(0xffffffffu, lg[r][o], 1);
            lg[r][o] += __shfl_xor_sync(0xffffffffu, lg[r][o], 2);
        }

    float ce = 0.f;
    if (t == 0) {
        const int bidx = 2 * bp + wn;
        #pragma unroll
        for (int mt = 0; mt < 2; mt++)
            #pragma unroll
            for (int h = 0; h < 2; h++) {
                const int gn = n0 + wm * 32 + mt * 16 + g + 8 * h;
                if (gn < NTEST) {
                    float logits[OUT_];
                    #pragma unroll
                    for (int o = 0; o < OUT_; o++)
                        logits[o] = lg[mt * 2 + h][o] + b2s[wn * 10 + o];
                    float m = logits[0];
                    #pragma unroll
                    for (int o = 1; o < OUT_; o++) m = fmaxf(m, logits[o]);
                    float s = 0.f;
                    #pragma unroll
                    for (int o = 0; o < OUT_; o++) s += expf(logits[o] - m);
                    float lse = m + logf(s);
                    int tg = tar2[(size_t)bidx * NTEST + gn];
                    float picked = 0.f;
                    #pragma unroll
                    for (int o = 0; o < OUT_; o++) picked = (o == tg) ? logits[o] : picked;
                    ce += lse - picked;
                }
            }
    }
    #pragma unroll
    for (int off = 16; off; off >>= 1) ce += __shfl_down_sync(0xffffffffu, ce, off);
    if (lane == 0) warpsum[wid] = ce;
    __syncthreads();
    if (tid == 0) {
        float tot = 0.f;
        #pragma unroll
        for (int i = 0; i < 8; i++) tot += warpsum[i];
        atomicAdd(&g_acc2, (double)tot);
    }
}

// ---------------- finalize: reduce loss1 partials + combine ----------------
__global__ __launch_bounds__(256) void fin_k(float* __restrict__ out) {
    __shared__ float ws[8];
    float s = 0.f;
    for (int i = threadIdx.x; i < PREPB; i += 256) s += g_l1part[i];
    #pragma unroll
    for (int off = 16; off; off >>= 1) s += __shfl_down_sync(0xffffffffu, s, off);
    int lane = threadIdx.x & 31, wrp = threadIdx.x >> 5;
    if (lane == 0) ws[wrp] = s;
    __syncthreads();
    if (threadIdx.x == 0) {
        float tot = 0.f;
        #pragma unroll
        for (int i = 0; i < 8; i++) tot += ws[i];
        float l1 = (float)(20.0 * ((double)tot / (double)((size_t)B_ * WVEC)));
        float l2 = (float)(g_acc2 / (double)((size_t)B_ * NTEST));
        out[0] = l1 + l2;
        out[1] = l1;
        out[2] = l2;
    }
}

extern "C" void kernel_launch(void* const* d_in, const int* in_sizes, int n_in,
                              void* d_out, int out_size) {
    const float* inp1   = (const float*)d_in[0];
    const float* tar1   = (const float*)d_in[1];
    const float* inp2   = (const float*)d_in[2];
    const int*   tar2   = (const int*)d_in[3];
    const float* images = (const float*)d_in[4];
    float* out = (float*)d_out;

    cudaFuncSetAttribute(mlp_ce_mma_k,
                         cudaFuncAttributeMaxDynamicSharedMemorySize, SMEM_TOT);

    prep_k<<<PREPB, 256>>>(images, inp2, inp1, tar1);
    dim3 grid(NTILE_, B_ / 2);
    mlp_ce_mma_k<<<grid, 256, SMEM_TOT>>>(inp2, tar2);
    fin_k<<<1, 256>>>(out);
}